// round 14
// baseline (speedup 1.0000x reference)
#include <cuda_runtime.h>
#include <math.h>
#include <stdint.h>

#define BGR 64
#define EPG  8192
#define EDG  524288
#define H 128
#define K1 1639
#define K2 1312
#define K3 1050
#define ACT 124
#define NMAX 131072

// ---------------- scratch ----------------
__device__ float g_buf0[(size_t)NMAX * H];
__device__ float g_buf1[(size_t)NMAX * H];
__device__ float g_xs[(size_t)NMAX * 4];
__device__ float g_sum4[(size_t)NMAX * 4];
__device__ int   g_cnt[NMAX];
__device__ int   g_rowstart[NMAX];
__device__ int   g_esrc[EDG];
__device__ int   g_edst[EDG];
__device__ int   g_evalid[EDG];
__device__ int   g_eadj[EDG];
__device__ float g_score[NMAX];
__device__ int   g_newpos[NMAX];
__device__ int   g_oldidx[NMAX];
__device__ float g_pnorm[4];
__device__ float g_accz[BGR * 256];

// ---------------- tiny utility kernels ----------------
__global__ void pnorm_kernel(const float* p1, const float* p2, const float* p3, float* out) {
    __shared__ float red[128];
    const float* ps[3] = {p1, p2, p3};
    int t = threadIdx.x;
    for (int l = 0; l < 3; l++) {
        red[t] = ps[l][t] * ps[l][t];
        __syncthreads();
        for (int off = 64; off; off >>= 1) {
            if (t < off) red[t] += red[t + off];
            __syncthreads();
        }
        if (t == 0) out[l] = sqrtf(red[0]);
        __syncthreads();
    }
}

// ---------------- level-0 fused: edge copy + degree count + xs + scan + fill ----------------
__global__ __launch_bounds__(1024) void init_build_l0(const int* __restrict__ src,
                                                      const int* __restrict__ dst,
                                                      int* __restrict__ esrc,
                                                      int* __restrict__ edst,
                                                      int* __restrict__ evalid,
                                                      int* __restrict__ cnt,
                                                      int* __restrict__ rowstart,
                                                      int* __restrict__ eadj,
                                                      const float* __restrict__ x,
                                                      float* __restrict__ xs) {
    __shared__ int c2[2048];
    __shared__ int cursor[2048];
    __shared__ int wsum[32];
    int g = blockIdx.x, t = threadIdx.x;
    int lane = t & 31, w = t >> 5;
    int nbase = g * 2048;
    int gb = g * EPG;
    c2[t] = 0; c2[t + 1024] = 0;
    __syncthreads();
    for (int e = gb + t; e < gb + EPG; e += 1024) {
        int s = src[e], d = dst[e];
        esrc[e] = s;
        edst[e] = d;
        evalid[e] = 1;
        atomicAdd(&c2[d - nbase], 1);
    }
    __syncthreads();
    int i0 = 2 * t, i1 = i0 + 1;
    int v0 = c2[i0], v1 = c2[i1];
    cnt[nbase + i0] = v0;
    cnt[nbase + i1] = v1;
    {
        float d0 = rsqrtf((float)(v0 + 1));
        float4 xi = *(const float4*)&x[(size_t)(nbase + i0) * 4];
        xi.x *= d0; xi.y *= d0; xi.z *= d0; xi.w *= d0;
        *(float4*)&xs[(size_t)(nbase + i0) * 4] = xi;
        float d1 = rsqrtf((float)(v1 + 1));
        float4 xj = *(const float4*)&x[(size_t)(nbase + i1) * 4];
        xj.x *= d1; xj.y *= d1; xj.z *= d1; xj.w *= d1;
        *(float4*)&xs[(size_t)(nbase + i1) * 4] = xj;
    }
    int pair = v0 + v1;
    int inc = pair;
#pragma unroll
    for (int o = 1; o < 32; o <<= 1) {
        int y = __shfl_up_sync(0xffffffffu, inc, o);
        if (lane >= o) inc += y;
    }
    if (lane == 31) wsum[w] = inc;
    __syncthreads();
    if (t < 32) {
        int a = wsum[t];
        int ai = a;
#pragma unroll
        for (int o = 1; o < 32; o <<= 1) {
            int y = __shfl_up_sync(0xffffffffu, ai, o);
            if (t >= o) ai += y;
        }
        wsum[t] = ai;
    }
    __syncthreads();
    int excl = inc - pair + ((w > 0) ? wsum[w - 1] : 0);
    cursor[i0] = excl;
    cursor[i1] = excl + v0;
    rowstart[nbase + i0] = gb + excl;
    rowstart[nbase + i1] = gb + excl + v0;
    __syncthreads();
    for (int e = gb + t; e < gb + EPG; e += 1024) {
        int d = edst[e] - nbase;
        int pos = atomicAdd(&cursor[d], 1);
        eadj[gb + pos] = esrc[e];
    }
}

// ---------------- tf32 GEMM helpers ----------------
__device__ __forceinline__ uint32_t f2tf(float f) {
    uint32_t u;
    asm("cvt.rna.tf32.f32 %0, %1;" : "=r"(u) : "f"(f));
    return u;
}

__device__ __forceinline__ void mma_tf32(float* c, uint32_t a0, uint32_t a1, uint32_t a2,
                                         uint32_t a3, uint32_t b0, uint32_t b1) {
    asm volatile(
        "mma.sync.aligned.m16n8k8.row.col.f32.tf32.tf32.f32 "
        "{%0,%1,%2,%3},{%4,%5,%6,%7},{%8,%9},{%0,%1,%2,%3};"
        : "+f"(c[0]), "+f"(c[1]), "+f"(c[2]), "+f"(c[3])
        : "r"(a0), "r"(a1), "r"(a2), "r"(a3), "r"(b0), "r"(b1));
}

// ---------------- combined: GEMM | per-graph CSR build ----------------
#define SHM_BYTES 20992
__global__ __launch_bounds__(256) void gemm_csr(const float* __restrict__ Hc,
                                                const int* __restrict__ oldidx,
                                                const float* __restrict__ score,
                                                const int* __restrict__ cnt,
                                                const float* __restrict__ W,
                                                float* __restrict__ Y, int n, int gemmBlocks,
                                                int* __restrict__ rowstart, int npg,
                                                const int* __restrict__ esrc,
                                                const int* __restrict__ edst,
                                                const int* __restrict__ evalid,
                                                int* __restrict__ eadj) {
    __shared__ __align__(16) char shm[SHM_BYTES];
    int tid = threadIdx.x;

    if ((int)blockIdx.x >= gemmBlocks) {
        int* cursor = (int*)shm;
        int* wsumc  = (int*)(shm + 8192);
        int g = blockIdx.x - gemmBlocks;
        int lane = tid & 31, w = tid >> 5;
        int nbase = g * npg;
        int gb = g * EPG;
        int base = tid * 8;
        int v[8], tot = 0;
#pragma unroll
        for (int j = 0; j < 8; j++) {
            int idx = base + j;
            v[j] = (idx < npg) ? cnt[nbase + idx] : 0;
            tot += v[j];
        }
        int inc = tot;
#pragma unroll
        for (int o = 1; o < 32; o <<= 1) {
            int y = __shfl_up_sync(0xffffffffu, inc, o);
            if (lane >= o) inc += y;
        }
        if (lane == 31) wsumc[w] = inc;
        __syncthreads();
        if (tid == 0) {
            int s = 0;
#pragma unroll
            for (int j = 0; j < 8; j++) { int tmp = wsumc[j]; wsumc[j] = s; s += tmp; }
        }
        __syncthreads();
        int run = inc - tot + wsumc[w];
#pragma unroll
        for (int j = 0; j < 8; j++) {
            int idx = base + j;
            cursor[idx] = run;
            if (idx < npg) rowstart[nbase + idx] = gb + run;
            run += v[j];
        }
        __syncthreads();
        for (int e = gb + tid; e < gb + EPG; e += 256) {
            if (evalid[e]) {
                int d = edst[e] - nbase;
                int pos = atomicAdd(&cursor[d], 1);
                eadj[gb + pos] = esrc[e];
            }
        }
        return;
    }

    uint32_t (*As)[128][12] = reinterpret_cast<uint32_t(*)[128][12]>(shm);
    uint32_t (*Bs)[8][136]  = reinterpret_cast<uint32_t(*)[8][136]>(shm + 12288);
    int bm = blockIdx.x * 128;
    int lane = tid & 31, warp = tid >> 5;
    int wr = warp >> 1, wc = warp & 1;

    float acc[2][8][4];
#pragma unroll
    for (int m = 0; m < 2; m++)
#pragma unroll
        for (int nt = 0; nt < 8; nt++)
#pragma unroll
            for (int q = 0; q < 4; q++) acc[m][nt][q] = 0.f;

    int arow = tid >> 1;
    int ac = (tid & 1) * 4;
    int browk = tid >> 5;
    int bcol = (tid & 31) * 4;

    int pos = bm + arow;
    bool rv = (pos < n);
    int o = 0;
    float sc = 0.f;
    if (rv) { o = oldidx[pos]; sc = score[o]; }
    const float* arowp = Hc + (size_t)o * 128;

    {
        float4 va = make_float4(0.f, 0.f, 0.f, 0.f);
        if (rv) va = *(const float4*)&arowp[ac];
        float4 vb = *(const float4*)&W[(size_t)browk * 128 + bcol];
        uint4 ua = make_uint4(f2tf(va.x * sc), f2tf(va.y * sc), f2tf(va.z * sc), f2tf(va.w * sc));
        uint4 ub = make_uint4(f2tf(vb.x), f2tf(vb.y), f2tf(vb.z), f2tf(vb.w));
        *(uint4*)&As[0][arow][ac] = ua;
        *(uint4*)&Bs[0][browk][bcol] = ub;
    }
    __syncthreads();

    int r0 = wr * 32 + (lane >> 2);
    int cA = lane & 3;

    for (int ks = 0; ks < 16; ks++) {
        int cur = ks & 1;
        float4 va, vb;
        if (ks < 15) {
            int k0 = (ks + 1) * 8;
            va = make_float4(0.f, 0.f, 0.f, 0.f);
            if (rv) va = *(const float4*)&arowp[k0 + ac];
            vb = *(const float4*)&W[(size_t)(k0 + browk) * 128 + bcol];
        }
        uint32_t bfr[8][2];
#pragma unroll
        for (int nt = 0; nt < 8; nt++) {
            int col = wc * 64 + nt * 8 + (lane >> 2);
            bfr[nt][0] = Bs[cur][lane & 3][col];
            bfr[nt][1] = Bs[cur][(lane & 3) + 4][col];
        }
#pragma unroll
        for (int m = 0; m < 2; m++) {
            uint32_t a0 = As[cur][r0 + m * 16][cA];
            uint32_t a1 = As[cur][r0 + m * 16 + 8][cA];
            uint32_t a2 = As[cur][r0 + m * 16][cA + 4];
            uint32_t a3 = As[cur][r0 + m * 16 + 8][cA + 4];
#pragma unroll
            for (int nt = 0; nt < 8; nt++)
                mma_tf32(acc[m][nt], a0, a1, a2, a3, bfr[nt][0], bfr[nt][1]);
        }
        if (ks < 15) {
            int nxt = cur ^ 1;
            uint4 ua = make_uint4(f2tf(va.x * sc), f2tf(va.y * sc), f2tf(va.z * sc), f2tf(va.w * sc));
            uint4 ub = make_uint4(f2tf(vb.x), f2tf(vb.y), f2tf(vb.z), f2tf(vb.w));
            *(uint4*)&As[nxt][arow][ac] = ua;
            *(uint4*)&Bs[nxt][browk][bcol] = ub;
            __syncthreads();
        }
    }

#pragma unroll
    for (int m = 0; m < 2; m++) {
        int row = bm + wr * 32 + m * 16 + (lane >> 2);
        float d0 = 0.f, d1 = 0.f;
        if (row < n)     d0 = rsqrtf((float)(cnt[row] + 1));
        if (row + 8 < n) d1 = rsqrtf((float)(cnt[row + 8] + 1));
#pragma unroll
        for (int nt = 0; nt < 8; nt++) {
            int col = wc * 64 + nt * 8 + (lane & 3) * 2;
            if (row < n)
                *(float2*)&Y[(size_t)row * 128 + col] =
                    make_float2(acc[m][nt][0] * d0, acc[m][nt][1] * d0);
            if (row + 8 < n)
                *(float2*)&Y[(size_t)(row + 8) * 128 + col] =
                    make_float2(acc[m][nt][2] * d1, acc[m][nt][3] * d1);
        }
    }
}

// ---------------- level-0: thread-per-node neighbor sum (4-wide unroll) ----------------
__global__ __launch_bounds__(256) void gcn_l0_sum(const float* __restrict__ xs,
                                                  const int* __restrict__ eadj,
                                                  const int* __restrict__ rowstart,
                                                  const int* __restrict__ cnt,
                                                  float* __restrict__ sum4, int n) {
    int i = blockIdx.x * 256 + threadIdx.x;
    if (i >= n) return;
    int c = cnt[i];
    int st = rowstart[i];
    float4 s = *(const float4*)&xs[(size_t)i * 4];
    int e = 0;
    for (; e + 3 < c; e += 4) {
        int iA = eadj[st + e], iB = eadj[st + e + 1];
        int iC = eadj[st + e + 2], iD = eadj[st + e + 3];
        float4 a = *(const float4*)&xs[(size_t)iA * 4];
        float4 b = *(const float4*)&xs[(size_t)iB * 4];
        float4 cc = *(const float4*)&xs[(size_t)iC * 4];
        float4 d = *(const float4*)&xs[(size_t)iD * 4];
        s.x += (a.x + b.x) + (cc.x + d.x);
        s.y += (a.y + b.y) + (cc.y + d.y);
        s.z += (a.z + b.z) + (cc.z + d.z);
        s.w += (a.w + b.w) + (cc.w + d.w);
    }
    for (; e < c; e++) {
        int iA = eadj[st + e];
        float4 a = *(const float4*)&xs[(size_t)iA * 4];
        s.x += a.x; s.y += a.y; s.z += a.z; s.w += a.w;
    }
    *(float4*)&sum4[(size_t)i * 4] = s;
}

// ---------------- level-0: warp-per-16-nodes matvec 4->128 (weights in regs) ----------------
__device__ __forceinline__ float warp_sum(float v) {
#pragma unroll
    for (int off = 16; off; off >>= 1) v += __shfl_xor_sync(0xffffffffu, v, off);
    return v;
}

#define L0_NPW 16
__global__ __launch_bounds__(256) void gcn_l0_fin(const float* __restrict__ sum4,
                                                  const float* __restrict__ W1,
                                                  const float* __restrict__ b1,
                                                  const int* __restrict__ cnt,
                                                  const float* __restrict__ p,
                                                  const float* __restrict__ pnorm,
                                                  float* __restrict__ Out,
                                                  float* __restrict__ score, int n) {
    int warp = blockIdx.x * 8 + (threadIdx.x >> 5);
    int lane = threadIdx.x & 31;
    int fb = lane * 4;
    int ibase = warp * L0_NPW;
    if (ibase >= n) return;

    float4 w0 = *(const float4*)&W1[fb];
    float4 w1 = *(const float4*)&W1[128 + fb];
    float4 w2 = *(const float4*)&W1[256 + fb];
    float4 w3 = *(const float4*)&W1[384 + fb];
    float4 bb = *(const float4*)&b1[fb];
    float4 pp = *(const float4*)&p[fb];
    float pn = pnorm[0];

#pragma unroll 4
    for (int j = 0; j < L0_NPW; j++) {
        int i = ibase + j;
        if (i >= n) break;
        float di = rsqrtf((float)(cnt[i] + 1));
        float4 sum = *(const float4*)&sum4[(size_t)i * 4];
        float4 acc;
        acc.x = fmaxf((sum.x * w0.x + sum.y * w1.x + sum.z * w2.x + sum.w * w3.x) * di + bb.x, 0.f);
        acc.y = fmaxf((sum.x * w0.y + sum.y * w1.y + sum.z * w2.y + sum.w * w3.y) * di + bb.y, 0.f);
        acc.z = fmaxf((sum.x * w0.z + sum.y * w1.z + sum.z * w2.z + sum.w * w3.z) * di + bb.z, 0.f);
        acc.w = fmaxf((sum.x * w0.w + sum.y * w1.w + sum.z * w2.w + sum.w * w3.w) * di + bb.w, 0.f);
        *(float4*)&Out[(size_t)i * H + fb] = acc;
        float sred = acc.x * pp.x + acc.y * pp.y + acc.z * pp.z + acc.w * pp.w;
        sred = warp_sum(sred);
        if (lane == 0) score[i] = tanhf(sred / pn);
    }
}

// ---------------- warp-per-node GCN gather (levels 1,2; 4-node outer, 4-wide inner) ----------------
#define L12_NPW 4
__global__ __launch_bounds__(256) void gcn_warp(const float* __restrict__ Ys,
                                                const int* __restrict__ eadj,
                                                const int* __restrict__ rowstart,
                                                const int* __restrict__ cnt,
                                                const float* __restrict__ bias,
                                                const float* __restrict__ p,
                                                const float* __restrict__ pnorm, int lvl,
                                                float* __restrict__ Out,
                                                float* __restrict__ score, int n) {
    int warp = blockIdx.x * 8 + (threadIdx.x >> 5);
    int lane = threadIdx.x & 31;
    int fb = lane * 4;
    int ibase = warp * L12_NPW;
    if (ibase >= n) return;

    float4 bb = *(const float4*)&bias[fb];
    float4 pp = *(const float4*)&p[fb];
    float pn = pnorm[lvl];

#pragma unroll
    for (int j = 0; j < L12_NPW; j++) {
        int i = ibase + j;
        if (i >= n) break;
        int c = cnt[i];
        float di = rsqrtf((float)(c + 1));
        float4 acc = *(const float4*)&Ys[(size_t)i * H + fb];
        int st = rowstart[i];
        int e = 0;
        for (; e + 3 < c; e += 4) {
            int iA = eadj[st + e], iB = eadj[st + e + 1];
            int iC = eadj[st + e + 2], iD = eadj[st + e + 3];
            float4 va = *(const float4*)&Ys[(size_t)iA * H + fb];
            float4 vb = *(const float4*)&Ys[(size_t)iB * H + fb];
            float4 vc = *(const float4*)&Ys[(size_t)iC * H + fb];
            float4 vd = *(const float4*)&Ys[(size_t)iD * H + fb];
            acc.x += (va.x + vb.x) + (vc.x + vd.x);
            acc.y += (va.y + vb.y) + (vc.y + vd.y);
            acc.z += (va.z + vb.z) + (vc.z + vd.z);
            acc.w += (va.w + vb.w) + (vc.w + vd.w);
        }
        for (; e < c; e++) {
            int iA = eadj[st + e];
            float4 va = *(const float4*)&Ys[(size_t)iA * H + fb];
            acc.x += va.x; acc.y += va.y; acc.z += va.z; acc.w += va.w;
        }
        acc.x = fmaxf(acc.x * di + bb.x, 0.f);
        acc.y = fmaxf(acc.y * di + bb.y, 0.f);
        acc.z = fmaxf(acc.z * di + bb.z, 0.f);
        acc.w = fmaxf(acc.w * di + bb.w, 0.f);
        *(float4*)&Out[(size_t)i * H + fb] = acc;
        float sred = acc.x * pp.x + acc.y * pp.y + acc.z * pp.z + acc.w * pp.w;
        sred = warp_sum(sred);
        if (lane == 0) score[i] = tanhf(sred / pn);
    }
}

// ---------------- radix-select top-k (proven) ----------------
__device__ __forceinline__ uint32_t fmap(float f) {
    uint32_t u = __float_as_uint(f);
    return (u & 0x80000000u) ? ~u : (u | 0x80000000u);
}

__device__ __forceinline__ void bscan2048(bool f0, bool f1, int* wsum, int t,
                                          int& p0, int& p1) {
    int w = t >> 5, lane = t & 31;
    unsigned b0 = __ballot_sync(0xffffffffu, f0);
    unsigned b1 = __ballot_sync(0xffffffffu, f1);
    if (lane == 0) { wsum[w] = __popc(b0); wsum[32 + w] = __popc(b1); }
    __syncthreads();
    if (t < 32) {
        int a = wsum[t], b = wsum[32 + t];
        int ai = a;
#pragma unroll
        for (int o = 1; o < 32; o <<= 1) { int y = __shfl_up_sync(0xffffffffu, ai, o); if (t >= o) ai += y; }
        int atot = __shfl_sync(0xffffffffu, ai, 31);
        int bi = b;
#pragma unroll
        for (int o = 1; o < 32; o <<= 1) { int y = __shfl_up_sync(0xffffffffu, bi, o); if (t >= o) bi += y; }
        bi += atot;
        wsum[t] = ai - a;
        wsum[32 + t] = bi - b;
    }
    __syncthreads();
    unsigned lm = (1u << lane) - 1;
    p0 = wsum[w] + __popc(b0 & lm);
    p1 = wsum[32 + w] + __popc(b1 & lm);
    __syncthreads();
}

__global__ __launch_bounds__(1024) void topk_radix(const float* __restrict__ score, int n, int kk,
                                                   int* __restrict__ newpos,
                                                   int* __restrict__ oldidx) {
    __shared__ uint32_t keys[2048];
    __shared__ int hist[256];
    __shared__ int cumsh[256];
    __shared__ int wsum[64];
    __shared__ int sh_b, sh_g;
    int g = blockIdx.x, t = threadIdx.x;
    int i1 = t + 1024;
    keys[t]  = (t  < n) ? fmap(score[g * n + t])  : 0u;
    keys[i1] = (i1 < n) ? fmap(score[g * n + i1]) : 0u;
    __syncthreads();

    uint32_t prefix = 0;
    int remaining = kk;
    for (int shift = 24; shift >= 0; shift -= 8) {
        if (t < 256) hist[t] = 0;
        __syncthreads();
        uint32_t k0 = keys[t], k1v = keys[i1];
        bool m0 = (shift == 24) || ((k0  >> (shift + 8)) == (prefix >> (shift + 8)));
        bool m1 = (shift == 24) || ((k1v >> (shift + 8)) == (prefix >> (shift + 8)));
        if (m0) atomicAdd(&hist[(k0  >> shift) & 255], 1);
        if (m1) atomicAdd(&hist[(k1v >> shift) & 255], 1);
        __syncthreads();
        int v = (t < 256) ? hist[255 - t] : 0;
        int x = v;
#pragma unroll
        for (int o = 1; o < 32; o <<= 1) { int y = __shfl_up_sync(0xffffffffu, x, o); if ((t & 31) >= o) x += y; }
        if ((t & 31) == 31 && t < 256) wsum[t >> 5] = x;
        __syncthreads();
        if (t < 32) {
            int w = (t < 8) ? wsum[t] : 0;
#pragma unroll
            for (int o = 1; o < 8; o <<= 1) { int y = __shfl_up_sync(0xffffffffu, w, o); if (t >= o) w += y; }
            if (t < 8) wsum[t] = w;
        }
        __syncthreads();
        if (t < 256) cumsh[t] = x + ((t >= 32) ? wsum[(t >> 5) - 1] : 0);
        __syncthreads();
        if (t < 256) {
            int Cb = cumsh[t];
            int Cn = (t == 0) ? 0 : cumsh[t - 1];
            if (Cb >= remaining && Cn < remaining) { sh_b = 255 - t; sh_g = Cn; }
        }
        __syncthreads();
        prefix |= ((uint32_t)sh_b) << shift;
        remaining -= sh_g;
        __syncthreads();
    }
    uint32_t T = prefix;
    int needEq = remaining;

    bool e0 = (keys[t] == T), e1 = (keys[i1] == T);
    int q0, q1;
    bscan2048(e0, e1, wsum, t, q0, q1);
    bool keep0 = (keys[t]  > T) || (e0 && q0 < needEq);
    bool keep1 = (keys[i1] > T) || (e1 && q1 < needEq);
    int p0, p1;
    bscan2048(keep0, keep1, wsum, t, p0, p1);
    if (t < n) {
        if (keep0) { newpos[g * n + t] = g * kk + p0; oldidx[g * kk + p0] = g * n + t; }
        else newpos[g * n + t] = -1;
    }
    if (i1 < n) {
        if (keep1) { newpos[g * n + i1] = g * kk + p1; oldidx[g * kk + p1] = g * n + i1; }
        else newpos[g * n + i1] = -1;
    }
}

// ---------------- combined: readout | remap ----------------
__global__ __launch_bounds__(1024) void readout_remap(const float* __restrict__ Hc,
                                                      const float* __restrict__ score,
                                                      const int* __restrict__ oldidx,
                                                      float* __restrict__ accz,
                                                      int k, int first,
                                                      int* __restrict__ esrc,
                                                      int* __restrict__ edst,
                                                      int* __restrict__ evalid,
                                                      const int* __restrict__ newpos,
                                                      int* __restrict__ cnt) {
    __shared__ float smax[8][128];
    __shared__ float ssum[8][128];
    __shared__ int c2[2048];
    int t = threadIdx.x;
    if ((int)blockIdx.x < BGR) {
        int g = blockIdx.x;
        int f = t & 127, c = t >> 7;
        float mx = -1e30f, sm = 0.f;
        for (int r = c; r < k; r += 8) {
            int o = oldidx[g * k + r];
            float v = Hc[(size_t)o * H + f] * score[o];
            mx = fmaxf(mx, v);
            sm += v;
        }
        smax[c][f] = mx;
        ssum[c][f] = sm;
        __syncthreads();
        if (c == 0) {
#pragma unroll
            for (int j = 1; j < 8; j++) {
                mx = fmaxf(mx, smax[j][f]);
                sm += ssum[j][f];
            }
            float mean = sm / (float)k;
            if (first) {
                accz[g * 256 + f] = mx;
                accz[g * 256 + 128 + f] = mean;
            } else {
                accz[g * 256 + f] += mx;
                accz[g * 256 + 128 + f] += mean;
            }
        }
    } else {
        int g = blockIdx.x - BGR;
        for (int j = t; j < k; j += 1024) c2[j] = 0;
        __syncthreads();
        int kb = g * k;
        int e0 = g * EPG;
        for (int e = e0 + t; e < e0 + EPG; e += 1024) {
            if (evalid[e]) {
                int s = newpos[esrc[e]];
                int d = newpos[edst[e]];
                if (s >= 0 && d >= 0) {
                    esrc[e] = s; edst[e] = d;
                    atomicAdd(&c2[d - kb], 1);
                } else {
                    esrc[e] = 0; edst[e] = 0; evalid[e] = 0;
                }
            }
        }
        __syncthreads();
        for (int j = t; j < k; j += 1024) cnt[kb + j] = c2[j];
    }
}

// ---------------- fused MLP head ----------------
__global__ void mlp_head(const float* __restrict__ accz,
                         const float* __restrict__ lw1, const float* __restrict__ lb1,
                         const float* __restrict__ lw2, const float* __restrict__ lb2,
                         const float* __restrict__ lw3, const float* __restrict__ lb3,
                         float* __restrict__ out) {
    int g = blockIdx.x, j = threadIdx.x;
    __shared__ float z0[256], z1s[128], z2s[64];
    z0[j] = accz[g * 256 + j];
    z0[128 + j] = accz[g * 256 + 128 + j];
    __syncthreads();
    float a = lb1[j];
    for (int q = 0; q < 256; q++) a += z0[q] * lw1[q * 128 + j];
    z1s[j] = fmaxf(a, 0.f);
    __syncthreads();
    if (j < 64) {
        float a2 = lb2[j];
        for (int q = 0; q < 128; q++) a2 += z1s[q] * lw2[q * 64 + j];
        z2s[j] = fmaxf(a2, 0.f);
    }
    __syncthreads();
    if (j < 124) {
        float a3 = lb3[j];
        for (int q = 0; q < 64; q++) a3 += z2s[q] * lw3[q * ACT + j];
        out[g * ACT + j] = 1.f / (1.f + expf(-a3));
    }
}

// ---------------- host orchestration ----------------
extern "C" void kernel_launch(void* const* d_in, const int* in_sizes, int n_in,
                              void* d_out, int out_size) {
    const float* x   = (const float*)d_in[0];
    const int* src   = (const int*)d_in[1];
    const int* dst   = (const int*)d_in[2];
    const float* W1  = (const float*)d_in[3];
    const float* b1  = (const float*)d_in[4];
    const float* W2  = (const float*)d_in[5];
    const float* b2  = (const float*)d_in[6];
    const float* W3  = (const float*)d_in[7];
    const float* b3  = (const float*)d_in[8];
    const float* p1  = (const float*)d_in[9];
    const float* p2  = (const float*)d_in[10];
    const float* p3  = (const float*)d_in[11];
    const float* lw1 = (const float*)d_in[12];
    const float* lb1 = (const float*)d_in[13];
    const float* lw2 = (const float*)d_in[14];
    const float* lb2 = (const float*)d_in[15];
    const float* lw3 = (const float*)d_in[16];
    const float* lb3 = (const float*)d_in[17];
    float* out = (float*)d_out;

    float *buf0, *buf1, *xs, *sum4, *score, *pnorm, *accz;
    int *cnt, *rowstart, *esrc, *edst, *evalid, *eadj, *newpos, *oldidx;
    cudaGetSymbolAddress((void**)&buf0, g_buf0);
    cudaGetSymbolAddress((void**)&buf1, g_buf1);
    cudaGetSymbolAddress((void**)&xs, g_xs);
    cudaGetSymbolAddress((void**)&sum4, g_sum4);
    cudaGetSymbolAddress((void**)&score, g_score);
    cudaGetSymbolAddress((void**)&pnorm, g_pnorm);
    cudaGetSymbolAddress((void**)&accz, g_accz);
    cudaGetSymbolAddress((void**)&cnt, g_cnt);
    cudaGetSymbolAddress((void**)&rowstart, g_rowstart);
    cudaGetSymbolAddress((void**)&esrc, g_esrc);
    cudaGetSymbolAddress((void**)&edst, g_edst);
    cudaGetSymbolAddress((void**)&evalid, g_evalid);
    cudaGetSymbolAddress((void**)&eadj, g_eadj);
    cudaGetSymbolAddress((void**)&newpos, g_newpos);
    cudaGetSymbolAddress((void**)&oldidx, g_oldidx);

    const int npg_[3] = {2048, 1639, 1312};
    const int kk_[3]  = {K1, K2, K3};
    const int nn[4]   = {131072, 64 * K1, 64 * K2, 64 * K3};
    const float* Ws[3] = {W1, W2, W3};
    const float* bs[3] = {b1, b2, b3};
    const float* ps[3] = {p1, p2, p3};

    pnorm_kernel<<<1, 128>>>(p1, p2, p3, pnorm);

    for (int l = 0; l < 3; l++) {
        int n = nn[l], k = kk_[l], npg = npg_[l];

        if (l == 0) {
            init_build_l0<<<BGR, 1024>>>(src, dst, esrc, edst, evalid, cnt,
                                         rowstart, eadj, x, xs);
            gcn_l0_sum<<<(n + 255) / 256, 256>>>(xs, eadj, rowstart, cnt, sum4, n);
            int w0 = (n + 8 * L0_NPW - 1) / (8 * L0_NPW);
            gcn_l0_fin<<<w0, 256>>>(sum4, W1, b1, cnt, p1, pnorm, buf1, score, n);
        } else {
            int gemmBlocks = (n + 127) / 128;
            gemm_csr<<<gemmBlocks + BGR, 256>>>(buf1, oldidx, score, cnt, Ws[l], buf0, n,
                                                gemmBlocks, rowstart, npg,
                                                esrc, edst, evalid, eadj);
            int w12 = (n + 8 * L12_NPW - 1) / (8 * L12_NPW);
            gcn_warp<<<w12, 256>>>(buf0, eadj, rowstart, cnt,
                                   bs[l], ps[l], pnorm, l, buf1, score, n);
        }

        topk_radix<<<BGR, 1024>>>(score, npg, k, newpos, oldidx);

        if (l < 2)
            readout_remap<<<2 * BGR, 1024>>>(buf1, score, oldidx, accz, k, (l == 0) ? 1 : 0,
                                             esrc, edst, evalid, newpos, cnt);
        else
            readout_remap<<<BGR, 1024>>>(buf1, score, oldidx, accz, k, 0,
                                         esrc, edst, evalid, newpos, cnt);
    }

    mlp_head<<<BGR, 128>>>(accz, lw1, lb1, lw2, lb2, lw3, lb3, out);
}

// round 15
// speedup vs baseline: 1.0291x; 1.0291x over previous
#include <cuda_runtime.h>
#include <math.h>
#include <stdint.h>

#define BGR 64
#define EPG  8192
#define EDG  524288
#define H 128
#define K1 1639
#define K2 1312
#define K3 1050
#define ACT 124
#define NMAX 131072

// ---------------- scratch ----------------
__device__ float g_buf0[(size_t)NMAX * H];
__device__ float g_buf1[(size_t)NMAX * H];
__device__ float g_xs[(size_t)NMAX * 4];
__device__ float g_sum4[(size_t)NMAX * 4];
__device__ int   g_cnt[NMAX];
__device__ int   g_rowstart[NMAX];
__device__ int   g_esrc[EDG];
__device__ int   g_edst[EDG];
__device__ int   g_evalid[EDG];
__device__ int   g_eadj[EDG];
__device__ float g_score[NMAX];
__device__ int   g_newpos[NMAX];
__device__ int   g_oldidx[NMAX];
__device__ float g_pnorm[4];
__device__ float g_accz[BGR * 256];

// ---------------- tiny utility kernels ----------------
__global__ void pnorm_kernel(const float* p1, const float* p2, const float* p3, float* out) {
    __shared__ float red[128];
    const float* ps[3] = {p1, p2, p3};
    int t = threadIdx.x;
    for (int l = 0; l < 3; l++) {
        red[t] = ps[l][t] * ps[l][t];
        __syncthreads();
        for (int off = 64; off; off >>= 1) {
            if (t < off) red[t] += red[t + off];
            __syncthreads();
        }
        if (t == 0) out[l] = sqrtf(red[0]);
        __syncthreads();
    }
}

// ---------------- level-0 fused: edge copy + degree count + xs + scan + fill ----------------
__global__ __launch_bounds__(1024) void init_build_l0(const int* __restrict__ src,
                                                      const int* __restrict__ dst,
                                                      int* __restrict__ esrc,
                                                      int* __restrict__ edst,
                                                      int* __restrict__ evalid,
                                                      int* __restrict__ cnt,
                                                      int* __restrict__ rowstart,
                                                      int* __restrict__ eadj,
                                                      const float* __restrict__ x,
                                                      float* __restrict__ xs) {
    __shared__ int c2[2048];
    __shared__ int cursor[2048];
    __shared__ int wsum[32];
    int g = blockIdx.x, t = threadIdx.x;
    int lane = t & 31, w = t >> 5;
    int nbase = g * 2048;
    int gb = g * EPG;
    c2[t] = 0; c2[t + 1024] = 0;
    __syncthreads();
    for (int e = gb + t; e < gb + EPG; e += 1024) {
        int s = src[e], d = dst[e];
        esrc[e] = s;
        edst[e] = d;
        evalid[e] = 1;
        atomicAdd(&c2[d - nbase], 1);
    }
    __syncthreads();
    int i0 = 2 * t, i1 = i0 + 1;
    int v0 = c2[i0], v1 = c2[i1];
    cnt[nbase + i0] = v0;
    cnt[nbase + i1] = v1;
    {
        float d0 = rsqrtf((float)(v0 + 1));
        float4 xi = *(const float4*)&x[(size_t)(nbase + i0) * 4];
        xi.x *= d0; xi.y *= d0; xi.z *= d0; xi.w *= d0;
        *(float4*)&xs[(size_t)(nbase + i0) * 4] = xi;
        float d1 = rsqrtf((float)(v1 + 1));
        float4 xj = *(const float4*)&x[(size_t)(nbase + i1) * 4];
        xj.x *= d1; xj.y *= d1; xj.z *= d1; xj.w *= d1;
        *(float4*)&xs[(size_t)(nbase + i1) * 4] = xj;
    }
    int pair = v0 + v1;
    int inc = pair;
#pragma unroll
    for (int o = 1; o < 32; o <<= 1) {
        int y = __shfl_up_sync(0xffffffffu, inc, o);
        if (lane >= o) inc += y;
    }
    if (lane == 31) wsum[w] = inc;
    __syncthreads();
    if (t < 32) {
        int a = wsum[t];
        int ai = a;
#pragma unroll
        for (int o = 1; o < 32; o <<= 1) {
            int y = __shfl_up_sync(0xffffffffu, ai, o);
            if (t >= o) ai += y;
        }
        wsum[t] = ai;
    }
    __syncthreads();
    int excl = inc - pair + ((w > 0) ? wsum[w - 1] : 0);
    cursor[i0] = excl;
    cursor[i1] = excl + v0;
    rowstart[nbase + i0] = gb + excl;
    rowstart[nbase + i1] = gb + excl + v0;
    __syncthreads();
    for (int e = gb + t; e < gb + EPG; e += 1024) {
        int d = edst[e] - nbase;
        int pos = atomicAdd(&cursor[d], 1);
        eadj[gb + pos] = esrc[e];
    }
}

// ---------------- tf32 GEMM helpers ----------------
__device__ __forceinline__ uint32_t f2tf(float f) {
    uint32_t u;
    asm("cvt.rna.tf32.f32 %0, %1;" : "=r"(u) : "f"(f));
    return u;
}

__device__ __forceinline__ void mma_tf32(float* c, uint32_t a0, uint32_t a1, uint32_t a2,
                                         uint32_t a3, uint32_t b0, uint32_t b1) {
    asm volatile(
        "mma.sync.aligned.m16n8k8.row.col.f32.tf32.tf32.f32 "
        "{%0,%1,%2,%3},{%4,%5,%6,%7},{%8,%9},{%0,%1,%2,%3};"
        : "+f"(c[0]), "+f"(c[1]), "+f"(c[2]), "+f"(c[3])
        : "r"(a0), "r"(a1), "r"(a2), "r"(a3), "r"(b0), "r"(b1));
}

// ---------------- combined: GEMM | per-graph CSR build ----------------
#define SHM_BYTES 20992
__global__ __launch_bounds__(256) void gemm_csr(const float* __restrict__ Hc,
                                                const int* __restrict__ oldidx,
                                                const float* __restrict__ score,
                                                const int* __restrict__ cnt,
                                                const float* __restrict__ W,
                                                float* __restrict__ Y, int n, int gemmBlocks,
                                                int* __restrict__ rowstart, int npg,
                                                const int* __restrict__ esrc,
                                                const int* __restrict__ edst,
                                                const int* __restrict__ evalid,
                                                int* __restrict__ eadj) {
    __shared__ __align__(16) char shm[SHM_BYTES];
    int tid = threadIdx.x;

    if ((int)blockIdx.x >= gemmBlocks) {
        int* cursor = (int*)shm;
        int* wsumc  = (int*)(shm + 8192);
        int g = blockIdx.x - gemmBlocks;
        int lane = tid & 31, w = tid >> 5;
        int nbase = g * npg;
        int gb = g * EPG;
        int base = tid * 8;
        int v[8], tot = 0;
#pragma unroll
        for (int j = 0; j < 8; j++) {
            int idx = base + j;
            v[j] = (idx < npg) ? cnt[nbase + idx] : 0;
            tot += v[j];
        }
        int inc = tot;
#pragma unroll
        for (int o = 1; o < 32; o <<= 1) {
            int y = __shfl_up_sync(0xffffffffu, inc, o);
            if (lane >= o) inc += y;
        }
        if (lane == 31) wsumc[w] = inc;
        __syncthreads();
        if (tid == 0) {
            int s = 0;
#pragma unroll
            for (int j = 0; j < 8; j++) { int tmp = wsumc[j]; wsumc[j] = s; s += tmp; }
        }
        __syncthreads();
        int run = inc - tot + wsumc[w];
#pragma unroll
        for (int j = 0; j < 8; j++) {
            int idx = base + j;
            cursor[idx] = run;
            if (idx < npg) rowstart[nbase + idx] = gb + run;
            run += v[j];
        }
        __syncthreads();
        for (int e = gb + tid; e < gb + EPG; e += 256) {
            if (evalid[e]) {
                int d = edst[e] - nbase;
                int pos = atomicAdd(&cursor[d], 1);
                eadj[gb + pos] = esrc[e];
            }
        }
        return;
    }

    uint32_t (*As)[128][12] = reinterpret_cast<uint32_t(*)[128][12]>(shm);
    uint32_t (*Bs)[8][136]  = reinterpret_cast<uint32_t(*)[8][136]>(shm + 12288);
    int bm = blockIdx.x * 128;
    int lane = tid & 31, warp = tid >> 5;
    int wr = warp >> 1, wc = warp & 1;

    float acc[2][8][4];
#pragma unroll
    for (int m = 0; m < 2; m++)
#pragma unroll
        for (int nt = 0; nt < 8; nt++)
#pragma unroll
            for (int q = 0; q < 4; q++) acc[m][nt][q] = 0.f;

    int arow = tid >> 1;
    int ac = (tid & 1) * 4;
    int browk = tid >> 5;
    int bcol = (tid & 31) * 4;

    int pos = bm + arow;
    bool rv = (pos < n);
    int o = 0;
    float sc = 0.f;
    if (rv) { o = oldidx[pos]; sc = score[o]; }
    const float* arowp = Hc + (size_t)o * 128;

    {
        float4 va = make_float4(0.f, 0.f, 0.f, 0.f);
        if (rv) va = *(const float4*)&arowp[ac];
        float4 vb = *(const float4*)&W[(size_t)browk * 128 + bcol];
        uint4 ua = make_uint4(f2tf(va.x * sc), f2tf(va.y * sc), f2tf(va.z * sc), f2tf(va.w * sc));
        uint4 ub = make_uint4(f2tf(vb.x), f2tf(vb.y), f2tf(vb.z), f2tf(vb.w));
        *(uint4*)&As[0][arow][ac] = ua;
        *(uint4*)&Bs[0][browk][bcol] = ub;
    }
    __syncthreads();

    int r0 = wr * 32 + (lane >> 2);
    int cA = lane & 3;

    for (int ks = 0; ks < 16; ks++) {
        int cur = ks & 1;
        float4 va, vb;
        if (ks < 15) {
            int k0 = (ks + 1) * 8;
            va = make_float4(0.f, 0.f, 0.f, 0.f);
            if (rv) va = *(const float4*)&arowp[k0 + ac];
            vb = *(const float4*)&W[(size_t)(k0 + browk) * 128 + bcol];
        }
        uint32_t bfr[8][2];
#pragma unroll
        for (int nt = 0; nt < 8; nt++) {
            int col = wc * 64 + nt * 8 + (lane >> 2);
            bfr[nt][0] = Bs[cur][lane & 3][col];
            bfr[nt][1] = Bs[cur][(lane & 3) + 4][col];
        }
#pragma unroll
        for (int m = 0; m < 2; m++) {
            uint32_t a0 = As[cur][r0 + m * 16][cA];
            uint32_t a1 = As[cur][r0 + m * 16 + 8][cA];
            uint32_t a2 = As[cur][r0 + m * 16][cA + 4];
            uint32_t a3 = As[cur][r0 + m * 16 + 8][cA + 4];
#pragma unroll
            for (int nt = 0; nt < 8; nt++)
                mma_tf32(acc[m][nt], a0, a1, a2, a3, bfr[nt][0], bfr[nt][1]);
        }
        if (ks < 15) {
            int nxt = cur ^ 1;
            uint4 ua = make_uint4(f2tf(va.x * sc), f2tf(va.y * sc), f2tf(va.z * sc), f2tf(va.w * sc));
            uint4 ub = make_uint4(f2tf(vb.x), f2tf(vb.y), f2tf(vb.z), f2tf(vb.w));
            *(uint4*)&As[nxt][arow][ac] = ua;
            *(uint4*)&Bs[nxt][browk][bcol] = ub;
            __syncthreads();
        }
    }

#pragma unroll
    for (int m = 0; m < 2; m++) {
        int row = bm + wr * 32 + m * 16 + (lane >> 2);
        float d0 = 0.f, d1 = 0.f;
        if (row < n)     d0 = rsqrtf((float)(cnt[row] + 1));
        if (row + 8 < n) d1 = rsqrtf((float)(cnt[row + 8] + 1));
#pragma unroll
        for (int nt = 0; nt < 8; nt++) {
            int col = wc * 64 + nt * 8 + (lane & 3) * 2;
            if (row < n)
                *(float2*)&Y[(size_t)row * 128 + col] =
                    make_float2(acc[m][nt][0] * d0, acc[m][nt][1] * d0);
            if (row + 8 < n)
                *(float2*)&Y[(size_t)(row + 8) * 128 + col] =
                    make_float2(acc[m][nt][2] * d1, acc[m][nt][3] * d1);
        }
    }
}

// ---------------- level-0: thread-per-node neighbor sum (4-wide unroll) ----------------
__global__ __launch_bounds__(256) void gcn_l0_sum(const float* __restrict__ xs,
                                                  const int* __restrict__ eadj,
                                                  const int* __restrict__ rowstart,
                                                  const int* __restrict__ cnt,
                                                  float* __restrict__ sum4, int n) {
    int i = blockIdx.x * 256 + threadIdx.x;
    if (i >= n) return;
    int c = cnt[i];
    int st = rowstart[i];
    float4 s = *(const float4*)&xs[(size_t)i * 4];
    int e = 0;
    for (; e + 3 < c; e += 4) {
        int iA = eadj[st + e], iB = eadj[st + e + 1];
        int iC = eadj[st + e + 2], iD = eadj[st + e + 3];
        float4 a = *(const float4*)&xs[(size_t)iA * 4];
        float4 b = *(const float4*)&xs[(size_t)iB * 4];
        float4 cc = *(const float4*)&xs[(size_t)iC * 4];
        float4 d = *(const float4*)&xs[(size_t)iD * 4];
        s.x += (a.x + b.x) + (cc.x + d.x);
        s.y += (a.y + b.y) + (cc.y + d.y);
        s.z += (a.z + b.z) + (cc.z + d.z);
        s.w += (a.w + b.w) + (cc.w + d.w);
    }
    for (; e < c; e++) {
        int iA = eadj[st + e];
        float4 a = *(const float4*)&xs[(size_t)iA * 4];
        s.x += a.x; s.y += a.y; s.z += a.z; s.w += a.w;
    }
    *(float4*)&sum4[(size_t)i * 4] = s;
}

// ---------------- level-0: warp-per-16-nodes matvec 4->128 (weights in regs) ----------------
__device__ __forceinline__ float warp_sum(float v) {
#pragma unroll
    for (int off = 16; off; off >>= 1) v += __shfl_xor_sync(0xffffffffu, v, off);
    return v;
}

#define L0_NPW 16
__global__ __launch_bounds__(256) void gcn_l0_fin(const float* __restrict__ sum4,
                                                  const float* __restrict__ W1,
                                                  const float* __restrict__ b1,
                                                  const int* __restrict__ cnt,
                                                  const float* __restrict__ p,
                                                  const float* __restrict__ pnorm,
                                                  float* __restrict__ Out,
                                                  float* __restrict__ score, int n) {
    int warp = blockIdx.x * 8 + (threadIdx.x >> 5);
    int lane = threadIdx.x & 31;
    int fb = lane * 4;
    int ibase = warp * L0_NPW;
    if (ibase >= n) return;

    float4 w0 = *(const float4*)&W1[fb];
    float4 w1 = *(const float4*)&W1[128 + fb];
    float4 w2 = *(const float4*)&W1[256 + fb];
    float4 w3 = *(const float4*)&W1[384 + fb];
    float4 bb = *(const float4*)&b1[fb];
    float4 pp = *(const float4*)&p[fb];
    float pn = pnorm[0];

#pragma unroll 4
    for (int j = 0; j < L0_NPW; j++) {
        int i = ibase + j;
        if (i >= n) break;
        float di = rsqrtf((float)(cnt[i] + 1));
        float4 sum = *(const float4*)&sum4[(size_t)i * 4];
        float4 acc;
        acc.x = fmaxf((sum.x * w0.x + sum.y * w1.x + sum.z * w2.x + sum.w * w3.x) * di + bb.x, 0.f);
        acc.y = fmaxf((sum.x * w0.y + sum.y * w1.y + sum.z * w2.y + sum.w * w3.y) * di + bb.y, 0.f);
        acc.z = fmaxf((sum.x * w0.z + sum.y * w1.z + sum.z * w2.z + sum.w * w3.z) * di + bb.z, 0.f);
        acc.w = fmaxf((sum.x * w0.w + sum.y * w1.w + sum.z * w2.w + sum.w * w3.w) * di + bb.w, 0.f);
        *(float4*)&Out[(size_t)i * H + fb] = acc;
        float sred = acc.x * pp.x + acc.y * pp.y + acc.z * pp.z + acc.w * pp.w;
        sred = warp_sum(sred);
        if (lane == 0) score[i] = tanhf(sred / pn);
    }
}

// ---------------- warp-per-node GCN gather (levels 1,2; 4-wide unroll; R13 proven) ----------------
__global__ __launch_bounds__(256) void gcn_warp(const float* __restrict__ Ys,
                                                const int* __restrict__ eadj,
                                                const int* __restrict__ rowstart,
                                                const int* __restrict__ cnt,
                                                const float* __restrict__ bias,
                                                const float* __restrict__ p,
                                                const float* __restrict__ pnorm, int lvl,
                                                float* __restrict__ Out,
                                                float* __restrict__ score, int n) {
    int i = blockIdx.x * 8 + (threadIdx.x >> 5);
    if (i >= n) return;
    int lane = threadIdx.x & 31;
    int fb = lane * 4;
    int c = cnt[i];
    float di = rsqrtf((float)(c + 1));
    float4 acc = *(const float4*)&Ys[(size_t)i * H + fb];

    int st = rowstart[i];
    int e = 0;
    for (; e + 3 < c; e += 4) {
        int iA = eadj[st + e], iB = eadj[st + e + 1];
        int iC = eadj[st + e + 2], iD = eadj[st + e + 3];
        float4 va = *(const float4*)&Ys[(size_t)iA * H + fb];
        float4 vb = *(const float4*)&Ys[(size_t)iB * H + fb];
        float4 vc = *(const float4*)&Ys[(size_t)iC * H + fb];
        float4 vd = *(const float4*)&Ys[(size_t)iD * H + fb];
        acc.x += (va.x + vb.x) + (vc.x + vd.x);
        acc.y += (va.y + vb.y) + (vc.y + vd.y);
        acc.z += (va.z + vb.z) + (vc.z + vd.z);
        acc.w += (va.w + vb.w) + (vc.w + vd.w);
    }
    for (; e < c; e++) {
        int iA = eadj[st + e];
        float4 va = *(const float4*)&Ys[(size_t)iA * H + fb];
        acc.x += va.x; acc.y += va.y; acc.z += va.z; acc.w += va.w;
    }
    float4 bb = *(const float4*)&bias[fb];
    acc.x = fmaxf(acc.x * di + bb.x, 0.f);
    acc.y = fmaxf(acc.y * di + bb.y, 0.f);
    acc.z = fmaxf(acc.z * di + bb.z, 0.f);
    acc.w = fmaxf(acc.w * di + bb.w, 0.f);
    *(float4*)&Out[(size_t)i * H + fb] = acc;

    float4 pp = *(const float4*)&p[fb];
    float sred = acc.x * pp.x + acc.y * pp.y + acc.z * pp.z + acc.w * pp.w;
    sred = warp_sum(sred);
    if (lane == 0) score[i] = tanhf(sred / pnorm[lvl]);
}

// ---------------- radix-select top-k (proven) ----------------
__device__ __forceinline__ uint32_t fmap(float f) {
    uint32_t u = __float_as_uint(f);
    return (u & 0x80000000u) ? ~u : (u | 0x80000000u);
}

__device__ __forceinline__ void bscan2048(bool f0, bool f1, int* wsum, int t,
                                          int& p0, int& p1) {
    int w = t >> 5, lane = t & 31;
    unsigned b0 = __ballot_sync(0xffffffffu, f0);
    unsigned b1 = __ballot_sync(0xffffffffu, f1);
    if (lane == 0) { wsum[w] = __popc(b0); wsum[32 + w] = __popc(b1); }
    __syncthreads();
    if (t < 32) {
        int a = wsum[t], b = wsum[32 + t];
        int ai = a;
#pragma unroll
        for (int o = 1; o < 32; o <<= 1) { int y = __shfl_up_sync(0xffffffffu, ai, o); if (t >= o) ai += y; }
        int atot = __shfl_sync(0xffffffffu, ai, 31);
        int bi = b;
#pragma unroll
        for (int o = 1; o < 32; o <<= 1) { int y = __shfl_up_sync(0xffffffffu, bi, o); if (t >= o) bi += y; }
        bi += atot;
        wsum[t] = ai - a;
        wsum[32 + t] = bi - b;
    }
    __syncthreads();
    unsigned lm = (1u << lane) - 1;
    p0 = wsum[w] + __popc(b0 & lm);
    p1 = wsum[32 + w] + __popc(b1 & lm);
    __syncthreads();
}

__global__ __launch_bounds__(1024) void topk_radix(const float* __restrict__ score, int n, int kk,
                                                   int* __restrict__ newpos,
                                                   int* __restrict__ oldidx) {
    __shared__ uint32_t keys[2048];
    __shared__ int hist[256];
    __shared__ int cumsh[256];
    __shared__ int wsum[64];
    __shared__ int sh_b, sh_g;
    int g = blockIdx.x, t = threadIdx.x;
    int i1 = t + 1024;
    keys[t]  = (t  < n) ? fmap(score[g * n + t])  : 0u;
    keys[i1] = (i1 < n) ? fmap(score[g * n + i1]) : 0u;
    __syncthreads();

    uint32_t prefix = 0;
    int remaining = kk;
    for (int shift = 24; shift >= 0; shift -= 8) {
        if (t < 256) hist[t] = 0;
        __syncthreads();
        uint32_t k0 = keys[t], k1v = keys[i1];
        bool m0 = (shift == 24) || ((k0  >> (shift + 8)) == (prefix >> (shift + 8)));
        bool m1 = (shift == 24) || ((k1v >> (shift + 8)) == (prefix >> (shift + 8)));
        if (m0) atomicAdd(&hist[(k0  >> shift) & 255], 1);
        if (m1) atomicAdd(&hist[(k1v >> shift) & 255], 1);
        __syncthreads();
        int v = (t < 256) ? hist[255 - t] : 0;
        int x = v;
#pragma unroll
        for (int o = 1; o < 32; o <<= 1) { int y = __shfl_up_sync(0xffffffffu, x, o); if ((t & 31) >= o) x += y; }
        if ((t & 31) == 31 && t < 256) wsum[t >> 5] = x;
        __syncthreads();
        if (t < 32) {
            int w = (t < 8) ? wsum[t] : 0;
#pragma unroll
            for (int o = 1; o < 8; o <<= 1) { int y = __shfl_up_sync(0xffffffffu, w, o); if (t >= o) w += y; }
            if (t < 8) wsum[t] = w;
        }
        __syncthreads();
        if (t < 256) cumsh[t] = x + ((t >= 32) ? wsum[(t >> 5) - 1] : 0);
        __syncthreads();
        if (t < 256) {
            int Cb = cumsh[t];
            int Cn = (t == 0) ? 0 : cumsh[t - 1];
            if (Cb >= remaining && Cn < remaining) { sh_b = 255 - t; sh_g = Cn; }
        }
        __syncthreads();
        prefix |= ((uint32_t)sh_b) << shift;
        remaining -= sh_g;
        __syncthreads();
    }
    uint32_t T = prefix;
    int needEq = remaining;

    bool e0 = (keys[t] == T), e1 = (keys[i1] == T);
    int q0, q1;
    bscan2048(e0, e1, wsum, t, q0, q1);
    bool keep0 = (keys[t]  > T) || (e0 && q0 < needEq);
    bool keep1 = (keys[i1] > T) || (e1 && q1 < needEq);
    int p0, p1;
    bscan2048(keep0, keep1, wsum, t, p0, p1);
    if (t < n) {
        if (keep0) { newpos[g * n + t] = g * kk + p0; oldidx[g * kk + p0] = g * n + t; }
        else newpos[g * n + t] = -1;
    }
    if (i1 < n) {
        if (keep1) { newpos[g * n + i1] = g * kk + p1; oldidx[g * kk + p1] = g * n + i1; }
        else newpos[g * n + i1] = -1;
    }
}

// ---------------- combined: readout | remap ----------------
__global__ __launch_bounds__(1024) void readout_remap(const float* __restrict__ Hc,
                                                      const float* __restrict__ score,
                                                      const int* __restrict__ oldidx,
                                                      float* __restrict__ accz,
                                                      int k, int first,
                                                      int* __restrict__ esrc,
                                                      int* __restrict__ edst,
                                                      int* __restrict__ evalid,
                                                      const int* __restrict__ newpos,
                                                      int* __restrict__ cnt) {
    __shared__ float smax[8][128];
    __shared__ float ssum[8][128];
    __shared__ int c2[2048];
    int t = threadIdx.x;
    if ((int)blockIdx.x < BGR) {
        int g = blockIdx.x;
        int f = t & 127, c = t >> 7;
        float mx = -1e30f, sm = 0.f;
        for (int r = c; r < k; r += 8) {
            int o = oldidx[g * k + r];
            float v = Hc[(size_t)o * H + f] * score[o];
            mx = fmaxf(mx, v);
            sm += v;
        }
        smax[c][f] = mx;
        ssum[c][f] = sm;
        __syncthreads();
        if (c == 0) {
#pragma unroll
            for (int j = 1; j < 8; j++) {
                mx = fmaxf(mx, smax[j][f]);
                sm += ssum[j][f];
            }
            float mean = sm / (float)k;
            if (first) {
                accz[g * 256 + f] = mx;
                accz[g * 256 + 128 + f] = mean;
            } else {
                accz[g * 256 + f] += mx;
                accz[g * 256 + 128 + f] += mean;
            }
        }
    } else {
        int g = blockIdx.x - BGR;
        for (int j = t; j < k; j += 1024) c2[j] = 0;
        __syncthreads();
        int kb = g * k;
        int e0 = g * EPG;
        for (int e = e0 + t; e < e0 + EPG; e += 1024) {
            if (evalid[e]) {
                int s = newpos[esrc[e]];
                int d = newpos[edst[e]];
                if (s >= 0 && d >= 0) {
                    esrc[e] = s; edst[e] = d;
                    atomicAdd(&c2[d - kb], 1);
                } else {
                    esrc[e] = 0; edst[e] = 0; evalid[e] = 0;
                }
            }
        }
        __syncthreads();
        for (int j = t; j < k; j += 1024) cnt[kb + j] = c2[j];
    }
}

// ---------------- fused MLP head ----------------
__global__ void mlp_head(const float* __restrict__ accz,
                         const float* __restrict__ lw1, const float* __restrict__ lb1,
                         const float* __restrict__ lw2, const float* __restrict__ lb2,
                         const float* __restrict__ lw3, const float* __restrict__ lb3,
                         float* __restrict__ out) {
    int g = blockIdx.x, j = threadIdx.x;
    __shared__ float z0[256], z1s[128], z2s[64];
    z0[j] = accz[g * 256 + j];
    z0[128 + j] = accz[g * 256 + 128 + j];
    __syncthreads();
    float a = lb1[j];
    for (int q = 0; q < 256; q++) a += z0[q] * lw1[q * 128 + j];
    z1s[j] = fmaxf(a, 0.f);
    __syncthreads();
    if (j < 64) {
        float a2 = lb2[j];
        for (int q = 0; q < 128; q++) a2 += z1s[q] * lw2[q * 64 + j];
        z2s[j] = fmaxf(a2, 0.f);
    }
    __syncthreads();
    if (j < 124) {
        float a3 = lb3[j];
        for (int q = 0; q < 64; q++) a3 += z2s[q] * lw3[q * ACT + j];
        out[g * ACT + j] = 1.f / (1.f + expf(-a3));
    }
}

// ---------------- host orchestration ----------------
extern "C" void kernel_launch(void* const* d_in, const int* in_sizes, int n_in,
                              void* d_out, int out_size) {
    const float* x   = (const float*)d_in[0];
    const int* src   = (const int*)d_in[1];
    const int* dst   = (const int*)d_in[2];
    const float* W1  = (const float*)d_in[3];
    const float* b1  = (const float*)d_in[4];
    const float* W2  = (const float*)d_in[5];
    const float* b2  = (const float*)d_in[6];
    const float* W3  = (const float*)d_in[7];
    const float* b3  = (const float*)d_in[8];
    const float* p1  = (const float*)d_in[9];
    const float* p2  = (const float*)d_in[10];
    const float* p3  = (const float*)d_in[11];
    const float* lw1 = (const float*)d_in[12];
    const float* lb1 = (const float*)d_in[13];
    const float* lw2 = (const float*)d_in[14];
    const float* lb2 = (const float*)d_in[15];
    const float* lw3 = (const float*)d_in[16];
    const float* lb3 = (const float*)d_in[17];
    float* out = (float*)d_out;

    float *buf0, *buf1, *xs, *sum4, *score, *pnorm, *accz;
    int *cnt, *rowstart, *esrc, *edst, *evalid, *eadj, *newpos, *oldidx;
    cudaGetSymbolAddress((void**)&buf0, g_buf0);
    cudaGetSymbolAddress((void**)&buf1, g_buf1);
    cudaGetSymbolAddress((void**)&xs, g_xs);
    cudaGetSymbolAddress((void**)&sum4, g_sum4);
    cudaGetSymbolAddress((void**)&score, g_score);
    cudaGetSymbolAddress((void**)&pnorm, g_pnorm);
    cudaGetSymbolAddress((void**)&accz, g_accz);
    cudaGetSymbolAddress((void**)&cnt, g_cnt);
    cudaGetSymbolAddress((void**)&rowstart, g_rowstart);
    cudaGetSymbolAddress((void**)&esrc, g_esrc);
    cudaGetSymbolAddress((void**)&edst, g_edst);
    cudaGetSymbolAddress((void**)&evalid, g_evalid);
    cudaGetSymbolAddress((void**)&eadj, g_eadj);
    cudaGetSymbolAddress((void**)&newpos, g_newpos);
    cudaGetSymbolAddress((void**)&oldidx, g_oldidx);

    const int npg_[3] = {2048, 1639, 1312};
    const int kk_[3]  = {K1, K2, K3};
    const int nn[4]   = {131072, 64 * K1, 64 * K2, 64 * K3};
    const float* Ws[3] = {W1, W2, W3};
    const float* bs[3] = {b1, b2, b3};
    const float* ps[3] = {p1, p2, p3};

    pnorm_kernel<<<1, 128>>>(p1, p2, p3, pnorm);

    for (int l = 0; l < 3; l++) {
        int n = nn[l], k = kk_[l], npg = npg_[l];

        if (l == 0) {
            init_build_l0<<<BGR, 1024>>>(src, dst, esrc, edst, evalid, cnt,
                                         rowstart, eadj, x, xs);
            gcn_l0_sum<<<(n + 255) / 256, 256>>>(xs, eadj, rowstart, cnt, sum4, n);
            int w0 = (n + 8 * L0_NPW - 1) / (8 * L0_NPW);
            gcn_l0_fin<<<w0, 256>>>(sum4, W1, b1, cnt, p1, pnorm, buf1, score, n);
        } else {
            int gemmBlocks = (n + 127) / 128;
            gemm_csr<<<gemmBlocks + BGR, 256>>>(buf1, oldidx, score, cnt, Ws[l], buf0, n,
                                                gemmBlocks, rowstart, npg,
                                                esrc, edst, evalid, eadj);
            gcn_warp<<<(n + 7) / 8, 256>>>(buf0, eadj, rowstart, cnt,
                                           bs[l], ps[l], pnorm, l, buf1, score, n);
        }

        topk_radix<<<BGR, 1024>>>(score, npg, k, newpos, oldidx);

        if (l < 2)
            readout_remap<<<2 * BGR, 1024>>>(buf1, score, oldidx, accz, k, (l == 0) ? 1 : 0,
                                             esrc, edst, evalid, newpos, cnt);
        else
            readout_remap<<<BGR, 1024>>>(buf1, score, oldidx, accz, k, 0,
                                         esrc, edst, evalid, newpos, cnt);
    }

    mlp_head<<<BGR, 128>>>(accz, lw1, lb1, lw2, lb2, lw3, lb3, out);
}